// round 4
// baseline (speedup 1.0000x reference)
#include <cuda_runtime.h>
#include <cuda_bf16.h>

#define NN 8192
#define T  64
#define NT (NN / T)   // 128

// Deterministic partial row sums: g_part[k][i] = degree contribution to row i
// from tile-column k. Written exactly once per slot. 4 MB scratch.
__device__ float g_part[NT * NN];
__device__ float g_dis[NN];

// ---------------------------------------------------------------------------
// Pass 1 (degrees): tile pair (bi <= bj). Only B = adj[J,I] staged in smem;
// A = adj[I,J] read straight from global in compute layout. Each smem element
// read exactly once; m accumulated into BOTH row partials (shfl-reduce) and
// column partials (per-thread register, since each thread owns one column).
// Thread map: c = t & 63 (column), rg = t >> 6 (16-row group).
// ---------------------------------------------------------------------------
__global__ __launch_bounds__(256) void pass1_degrees(const float* __restrict__ adj) {
    const int bi = blockIdx.y, bj = blockIdx.x;
    if (bj < bi) return;

    __shared__ float Bs[T][T + 1];
    __shared__ float rpart[T][2];
    __shared__ float cpart[4][T];

    const int t    = threadIdx.x;
    const int c    = t & 63;
    const int rg   = t >> 6;
    const int half = (t >> 5) & 1;        // which 32-column half this warp covers
    const size_t I0 = (size_t)bi * T, J0 = (size_t)bj * T;

    // Load B tile (coalesced; STS bank = (rr + c) % 32 via lane-c spread -> conflict-free)
    #pragma unroll
    for (int k = 0; k < 16; ++k) {
        int rr = rg * 16 + k;
        Bs[rr][c] = adj[(J0 + rr) * NN + I0 + c];
    }
    __syncthreads();

    const bool diag = (bi == bj);
    float colAcc = 0.0f;

    #pragma unroll
    for (int k = 0; k < 16; ++k) {
        int r = rg * 16 + k;
        float a = adj[(I0 + r) * NN + J0 + c];          // coalesced
        float m = fmaxf(a, Bs[c][r]);                    // bank (c+r)%32 -> conflict-free
        if (diag && r == c) m = 1.0f;
        colAcc += m;
        float s = m;                                     // row-sum reduce across the 32 lanes (c-half)
        s += __shfl_xor_sync(0xffffffffu, s, 1);
        s += __shfl_xor_sync(0xffffffffu, s, 2);
        s += __shfl_xor_sync(0xffffffffu, s, 4);
        s += __shfl_xor_sync(0xffffffffu, s, 8);
        s += __shfl_xor_sync(0xffffffffu, s, 16);
        if ((t & 31) == 0) rpart[r][half] = s;
    }
    cpart[rg][c] = colAcc;
    __syncthreads();

    if (t < T) {
        g_part[bj * NN + I0 + t] = rpart[t][0] + rpart[t][1];
        if (!diag)
            g_part[bi * NN + J0 + t] = cpart[0][t] + cpart[1][t] + cpart[2][t] + cpart[3][t];
    }
}

// ---------------------------------------------------------------------------
// Reduce the 128 partials per row, rsqrt. Coalesced.
// ---------------------------------------------------------------------------
__global__ __launch_bounds__(256) void reduce_rsqrt_kernel() {
    const int i = blockIdx.x * blockDim.x + threadIdx.x;
    if (i >= NN) return;
    float s = 0.0f;
    #pragma unroll 8
    for (int k = 0; k < NT; ++k)
        s += g_part[k * NN + i];
    g_dis[i] = rsqrtf(s);
}

// ---------------------------------------------------------------------------
// Pass 2 (write): out is SYMMETRIC, so the (J,I) block is the transpose of
// the (I,J) block. Compute scaled value s once, write out[I,J] coalesced,
// stage s in place over the Bs slot just read (bijective per-thread read ->
// no hazard), then one transposed conflict-free re-read writes out[J,I].
// Blocks walk tile pairs in REVERSE of pass1 order for L2 reuse.
// ---------------------------------------------------------------------------
__global__ __launch_bounds__(256) void pass2_write(const float* __restrict__ adj,
                                                   float* __restrict__ out) {
    const int bx = blockIdx.x, by = blockIdx.y;
    if (bx > by) return;                  // reversed triangle
    const int bi = NT - 1 - by, bj = NT - 1 - bx;   // bj >= bi

    __shared__ float Bs[T][T + 1];
    __shared__ float dI[T], dJ[T];

    const int t  = threadIdx.x;
    const int c  = t & 63;
    const int rg = t >> 6;
    const size_t I0 = (size_t)bi * T, J0 = (size_t)bj * T;

    #pragma unroll
    for (int k = 0; k < 16; ++k) {
        int rr = rg * 16 + k;
        Bs[rr][c] = adj[(J0 + rr) * NN + I0 + c];
    }
    if (t < T)          dI[t]     = g_dis[I0 + t];
    else if (t < 2 * T) dJ[t - T] = g_dis[J0 + (t - T)];
    __syncthreads();

    const bool diag = (bi == bj);
    const float djc = dJ[c];

    #pragma unroll
    for (int k = 0; k < 16; ++k) {
        int r = rg * 16 + k;
        float a = adj[(I0 + r) * NN + J0 + c];
        float m = fmaxf(a, Bs[c][r]);
        if (diag && r == c) m = 1.0f;
        float s = m * dI[r] * djc;
        out[(I0 + r) * NN + J0 + c] = s;  // coalesced
        Bs[c][r] = s;                     // stage transposed (same slot just read)
    }

    if (!diag) {
        __syncthreads();
        #pragma unroll
        for (int k = 0; k < 16; ++k) {
            int rr = rg * 16 + k;         // row within the (J,I) block
            out[(J0 + rr) * NN + I0 + c] = Bs[rr][c];   // conflict-free, coalesced
        }
    }
}

extern "C" void kernel_launch(void* const* d_in, const int* in_sizes, int n_in,
                              void* d_out, int out_size) {
    const float* adj = (const float*)d_in[0];
    float*       out = (float*)d_out;

    dim3 grid(NT, NT);
    pass1_degrees<<<grid, 256>>>(adj);
    reduce_rsqrt_kernel<<<NN / 256, 256>>>();
    pass2_write<<<grid, 256>>>(adj, out);
}

// round 5
// speedup vs baseline: 1.0062x; 1.0062x over previous
#include <cuda_runtime.h>
#include <cuda_bf16.h>

#define NN 8192
#define T  64
#define NT (NN / T)   // 128

// Deterministic partial row sums: g_part[k][i] = degree contribution to row i
// from tile-column k. Written exactly once per slot. 4 MB scratch.
__device__ float g_part[NT * NN];
__device__ float g_dis[NN];

// ---------------------------------------------------------------------------
// Pass 1 (degrees): tile pair (bi <= bj). Only B = adj[J,I] staged in smem;
// A = adj[I,J] read straight from global in compute layout. Each smem element
// read exactly once; m accumulated into BOTH row partials (shfl-reduce) and
// column partials (per-thread register, since each thread owns one column).
// Thread map: c = t & 63 (column), rg = t >> 6 (16-row group).
// ---------------------------------------------------------------------------
__global__ __launch_bounds__(256) void pass1_degrees(const float* __restrict__ adj) {
    const int bi = blockIdx.y, bj = blockIdx.x;
    if (bj < bi) return;

    __shared__ float Bs[T][T + 1];
    __shared__ float rpart[T][2];
    __shared__ float cpart[4][T];

    const int t    = threadIdx.x;
    const int c    = t & 63;
    const int rg   = t >> 6;
    const int half = (t >> 5) & 1;        // which 32-column half this warp covers
    const size_t I0 = (size_t)bi * T, J0 = (size_t)bj * T;

    // Load B tile (coalesced; STS bank = (rr + c) % 32 via lane-c spread -> conflict-free)
    #pragma unroll
    for (int k = 0; k < 16; ++k) {
        int rr = rg * 16 + k;
        Bs[rr][c] = adj[(J0 + rr) * NN + I0 + c];
    }
    __syncthreads();

    const bool diag = (bi == bj);
    float colAcc = 0.0f;

    #pragma unroll
    for (int k = 0; k < 16; ++k) {
        int r = rg * 16 + k;
        float a = adj[(I0 + r) * NN + J0 + c];          // coalesced
        float m = fmaxf(a, Bs[c][r]);                    // bank (c+r)%32 -> conflict-free
        if (diag && r == c) m = 1.0f;
        colAcc += m;
        float s = m;                                     // row-sum reduce across the 32 lanes (c-half)
        s += __shfl_xor_sync(0xffffffffu, s, 1);
        s += __shfl_xor_sync(0xffffffffu, s, 2);
        s += __shfl_xor_sync(0xffffffffu, s, 4);
        s += __shfl_xor_sync(0xffffffffu, s, 8);
        s += __shfl_xor_sync(0xffffffffu, s, 16);
        if ((t & 31) == 0) rpart[r][half] = s;
    }
    cpart[rg][c] = colAcc;
    __syncthreads();

    if (t < T) {
        g_part[bj * NN + I0 + t] = rpart[t][0] + rpart[t][1];
        if (!diag)
            g_part[bi * NN + J0 + t] = cpart[0][t] + cpart[1][t] + cpart[2][t] + cpart[3][t];
    }
}

// ---------------------------------------------------------------------------
// Reduce the 128 partials per row, rsqrt. Coalesced.
// ---------------------------------------------------------------------------
__global__ __launch_bounds__(256) void reduce_rsqrt_kernel() {
    const int i = blockIdx.x * blockDim.x + threadIdx.x;
    if (i >= NN) return;
    float s = 0.0f;
    #pragma unroll 8
    for (int k = 0; k < NT; ++k)
        s += g_part[k * NN + i];
    g_dis[i] = rsqrtf(s);
}

// ---------------------------------------------------------------------------
// Pass 2 (write): out is SYMMETRIC, so the (J,I) block is the transpose of
// the (I,J) block. Compute scaled value s once, write out[I,J] coalesced,
// stage s in place over the Bs slot just read (bijective per-thread read ->
// no hazard), then one transposed conflict-free re-read writes out[J,I].
// Blocks walk tile pairs in REVERSE of pass1 order for L2 reuse.
// ---------------------------------------------------------------------------
__global__ __launch_bounds__(256) void pass2_write(const float* __restrict__ adj,
                                                   float* __restrict__ out) {
    const int bx = blockIdx.x, by = blockIdx.y;
    if (bx > by) return;                  // reversed triangle
    const int bi = NT - 1 - by, bj = NT - 1 - bx;   // bj >= bi

    __shared__ float Bs[T][T + 1];
    __shared__ float dI[T], dJ[T];

    const int t  = threadIdx.x;
    const int c  = t & 63;
    const int rg = t >> 6;
    const size_t I0 = (size_t)bi * T, J0 = (size_t)bj * T;

    #pragma unroll
    for (int k = 0; k < 16; ++k) {
        int rr = rg * 16 + k;
        Bs[rr][c] = adj[(J0 + rr) * NN + I0 + c];
    }
    if (t < T)          dI[t]     = g_dis[I0 + t];
    else if (t < 2 * T) dJ[t - T] = g_dis[J0 + (t - T)];
    __syncthreads();

    const bool diag = (bi == bj);
    const float djc = dJ[c];

    #pragma unroll
    for (int k = 0; k < 16; ++k) {
        int r = rg * 16 + k;
        float a = adj[(I0 + r) * NN + J0 + c];
        float m = fmaxf(a, Bs[c][r]);
        if (diag && r == c) m = 1.0f;
        float s = m * dI[r] * djc;
        out[(I0 + r) * NN + J0 + c] = s;  // coalesced
        Bs[c][r] = s;                     // stage transposed (same slot just read)
    }

    if (!diag) {
        __syncthreads();
        #pragma unroll
        for (int k = 0; k < 16; ++k) {
            int rr = rg * 16 + k;         // row within the (J,I) block
            out[(J0 + rr) * NN + I0 + c] = Bs[rr][c];   // conflict-free, coalesced
        }
    }
}

extern "C" void kernel_launch(void* const* d_in, const int* in_sizes, int n_in,
                              void* d_out, int out_size) {
    const float* adj = (const float*)d_in[0];
    float*       out = (float*)d_out;

    dim3 grid(NT, NT);
    pass1_degrees<<<grid, 256>>>(adj);
    reduce_rsqrt_kernel<<<NN / 256, 256>>>();
    pass2_write<<<grid, 256>>>(adj, out);
}